// round 1
// baseline (speedup 1.0000x reference)
#include <cuda_runtime.h>
#include <stdint.h>

// GLCMAttention: per (b,c) image -> 4-angle GLCM (8 gray levels, zero-padded
// shifts) -> [contrast, homogeneity, energy, correlation] x 4 -> relu(f@W1)
// -> sigmoid(h@W2) diagonal -> out = x * (1 + w).
//
// One block per (b,c) image (512 blocks x 256 threads).
// smem layout (dynamic):
//   qbuf : 257 rows x 264 bytes (quantized image + zero guards + zero row 256)
//   hist : per-thread uint16 histograms, lane-owns-bank layout, 128 KiB
//   totals[256], feats[16], scale

#define ROWSTRIDE 264
#define QBUF_BYTES (257 * ROWSTRIDE)        // 67848
#define QBUF_PAD   67968                    // aligned
#define HIST_BYTES 131072
#define SMEM_TOTAL (QBUF_PAD + HIST_BYTES + 256*4 + 16*4 + 64)

__global__ void __launch_bounds__(256, 1)
glcm_attn_kernel(const float* __restrict__ x,
                 const float* __restrict__ W1,
                 const float* __restrict__ W2,
                 float* __restrict__ out)
{
    extern __shared__ unsigned char smem[];
    unsigned char* qb   = smem;
    unsigned char* hist = smem + QBUF_PAD;
    unsigned int*  totals = (unsigned int*)(smem + QBUF_PAD + HIST_BYTES);
    float*         feats  = (float*)(totals + 256);
    float*         scalep = feats + 16;

    const int t  = threadIdx.x;
    const int bc = blockIdx.x;
    const float* xp = x   + (size_t)bc * 65536;
    float*       op = out + (size_t)bc * 65536;

    // ---- zero per-thread histograms (131072 B = 8192 uint4) ----
    uint4* h4 = (uint4*)hist;
    #pragma unroll
    for (int i = 0; i < 32; ++i) h4[t + (i << 8)] = make_uint4(0u, 0u, 0u, 0u);

    // ---- zero guards: word 0 (left guard byte 3) and word 65 (right guard) of rows 0..255
    ((unsigned int*)(qb + t * ROWSTRIDE))[0]  = 0u;
    ((unsigned int*)(qb + t * ROWSTRIDE))[65] = 0u;
    // zero entire row 256 (66 words)
    if (t < 66) ((unsigned int*)(qb + 256 * ROWSTRIDE))[t] = 0u;

    // ---- stage: load x as float4, quantize (trunc(x*7)), pack 4 bytes -> smem
    #pragma unroll 4
    for (int k = 0; k < 64; ++k) {
        int i = t + (k << 8);                    // float4 index, coalesced
        float4 v = ((const float4*)xp)[i];
        int pix = i << 2;
        int row = pix >> 8;
        int col = pix & 255;
        unsigned int q0 = (unsigned int)(int)(v.x * 7.0f);
        unsigned int q1 = (unsigned int)(int)(v.y * 7.0f);
        unsigned int q2 = (unsigned int)(int)(v.z * 7.0f);
        unsigned int q3 = (unsigned int)(int)(v.w * 7.0f);
        unsigned int packed = q0 | (q1 << 8) | (q2 << 16) | (q3 << 24);
        *(unsigned int*)(qb + row * ROWSTRIDE + 4 + col) = packed;
    }
    __syncthreads();

    // ---- histogram: thread t owns column x=t, walks 256 rows.
    // Counter c = angle*64 + q*8 + qs. Byte address (conflict-free, lane owns bank):
    //   addr = tg*16384 + lane*4 + abase[angle] + (q<<10) + (qs<<7)
    //   abase = {0, 8192, 2, 8194}  (angles 2,3 use halfword 1)
    {
        const unsigned int lane = t & 31, tg = t >> 5;
        unsigned char* hb = hist + tg * 16384 + lane * 4;

        unsigned int n1 = qb[3 + t];    // q[0][x-1]
        unsigned int n2 = qb[4 + t];    // q[0][x]
        unsigned int n3 = qb[5 + t];    // q[0][x+1] (unused as current)
        (void)n3;
        unsigned int rb = ROWSTRIDE;

        #pragma unroll 4
        for (int y = 0; y < 256; ++y) {
            unsigned int ql = n1, qc = n2;
            n1 = qb[rb + 3 + t];        // q[y+1][x-1]
            n2 = qb[rb + 4 + t];        // q[y+1][x]
            n3 = qb[rb + 5 + t];        // q[y+1][x+1]
            rb += ROWSTRIDE;

            unsigned int qh = qc << 10;
            unsigned short* p0 = (unsigned short*)(hb + 0u    + qh + (ql << 7));
            unsigned short* p1 = (unsigned short*)(hb + 8192u + qh + (n1 << 7));
            unsigned short* p2 = (unsigned short*)(hb + 2u    + qh + (n2 << 7));
            unsigned short* p3 = (unsigned short*)(hb + 8194u + qh + (n3 << 7));
            unsigned short v0 = *p0, v1 = *p1, v2 = *p2, v3 = *p3;
            *p0 = (unsigned short)(v0 + 1u);
            *p1 = (unsigned short)(v1 + 1u);
            *p2 = (unsigned short)(v2 + 1u);
            *p3 = (unsigned short)(v3 + 1u);
        }
    }
    __syncthreads();

    // ---- reduce per-thread hists: thread t<128 sums counter t (lo halfword)
    //      and t+128 (hi halfword) across all 256 threads.
    if (t < 128) {
        unsigned int slo = 0, shi = 0;
        const unsigned int* hw = (const unsigned int*)hist;
        unsigned int base = (unsigned int)t * 32u;
        #pragma unroll
        for (int tg2 = 0; tg2 < 8; ++tg2) {
            unsigned int wb = (unsigned int)tg2 * 4096u + base;
            #pragma unroll 8
            for (int l = 0; l < 32; ++l) {
                unsigned int lw = (unsigned int)(l + t) & 31u;   // stagger banks
                unsigned int w = hw[wb + lw];
                slo += w & 0xFFFFu;
                shi += w >> 16;
            }
        }
        totals[t]       = slo;
        totals[t + 128] = shi;
    }
    __syncthreads();

    // ---- features: warp 0, lane l -> angle = l>>3, row i = l&7 (8 bins each)
    if (t < 32) {
        int angle = t >> 3;
        int sub   = t & 7;
        const float inv = 1.0f / 65536.0f;
        float fi = (float)sub;
        float contrast = 0.f, homog = 0.f, energy = 0.f, corr = 0.f;
        #pragma unroll
        for (int j = 0; j < 8; ++j) {
            float p = (float)totals[angle * 64 + sub * 8 + j] * inv;
            float d = fi - (float)j;
            contrast += d * d * p;
            homog    += p / (1.0f + fabsf(d));
            energy   += p * p;
            corr     += (fi - 3.5f) * ((float)j - 3.5f) * p;
        }
        #pragma unroll
        for (int off = 4; off; off >>= 1) {
            contrast += __shfl_down_sync(0xFFFFFFFFu, contrast, off);
            homog    += __shfl_down_sync(0xFFFFFFFFu, homog,    off);
            energy   += __shfl_down_sync(0xFFFFFFFFu, energy,   off);
            corr     += __shfl_down_sync(0xFFFFFFFFu, corr,     off);
        }
        if (sub == 0) {
            feats[angle * 4 + 0] = contrast;
            feats[angle * 4 + 1] = homog;
            feats[angle * 4 + 2] = energy;
            feats[angle * 4 + 3] = corr * (1.0f / 6.000001f);  // / (std^2 + 1e-6)
        }
    }
    __syncthreads();

    // ---- MLP diagonal: h_k = relu(sum_f feats[f]*W1[f,k]); w = sigmoid(sum_k h_k*W2[k,c])
    if (t < 16) {
        float h = 0.f;
        #pragma unroll
        for (int f = 0; f < 16; ++f) h += feats[f] * W1[f * 16 + t];
        h = fmaxf(h, 0.0f);
        int c = bc & 63;
        float v = h * W2[t * 64 + c];
        #pragma unroll
        for (int off = 8; off; off >>= 1)
            v += __shfl_down_sync(0x0000FFFFu, v, off);
        if (t == 0) {
            float s = 1.0f / (1.0f + expf(-v));
            *scalep = 1.0f + s;
        }
    }
    __syncthreads();

    // ---- output: out = x * scale (x re-read, mostly L2-hot)
    const float s = *scalep;
    #pragma unroll 4
    for (int k = 0; k < 64; ++k) {
        int i = t + (k << 8);
        float4 v = ((const float4*)xp)[i];
        v.x *= s; v.y *= s; v.z *= s; v.w *= s;
        ((float4*)op)[i] = v;
    }
}

extern "C" void kernel_launch(void* const* d_in, const int* in_sizes, int n_in,
                              void* d_out, int out_size)
{
    (void)in_sizes; (void)n_in; (void)out_size;
    const float* x  = (const float*)d_in[0];
    const float* W1 = (const float*)d_in[1];
    const float* W2 = (const float*)d_in[2];
    float* out = (float*)d_out;

    cudaFuncSetAttribute(glcm_attn_kernel,
                         cudaFuncAttributeMaxDynamicSharedMemorySize, SMEM_TOTAL);
    glcm_attn_kernel<<<512, 256, SMEM_TOTAL>>>(x, W1, W2, out);
}